// round 2
// baseline (speedup 1.0000x reference)
#include <cuda_runtime.h>
#include <cstdint>

// Problem constants
#define BB 4
#define SS 4096
#define DD 2048
#define RR 4
#define RFF 16
#define NROWS (BB*SS)   // 16384
#define TR 4            // rows per block tile
#define EPS 1e-6f

typedef unsigned long long u64;

// -------- scratch (no allocation allowed -> __device__ globals) --------
__device__ __align__(16) float g_u[NROWS*RR];     // 256 KB
__device__ __align__(16) float g_h[NROWS*RR];     // 256 KB
__device__ __align__(16) float g_Vt[RR*DD];       // Vt[r][d] = w[d]*V[d][r]
__device__ __align__(16) float g_Ut[RR*DD];       // Ut[r][d] = U[d][r]
__device__ __align__(16) float g_W1t[RFF*DD];     // W1t[r][d] = w[d]*W1[d][r]
__device__ float g_a[RR];

// -------- f32x2 packed math (Blackwell; ptxas won't auto-fuse) --------
__device__ __forceinline__ u64 fma2(u64 a, u64 b, u64 c){
    u64 d;
    asm("fma.rn.f32x2 %0, %1, %2, %3;" : "=l"(d) : "l"(a), "l"(b), "l"(c));
    return d;
}
__device__ __forceinline__ u64 pack2(float x, float y){
    u64 r; asm("mov.b64 %0, {%1, %2};" : "=l"(r) : "f"(x), "f"(y)); return r;
}
__device__ __forceinline__ float2 unpack2(u64 p){
    float2 f; asm("mov.b64 {%0, %1}, %2;" : "=f"(f.x), "=f"(f.y) : "l"(p)); return f;
}

__device__ __forceinline__ float warp_sum(float v){
    v += __shfl_down_sync(0xffffffffu, v, 16);
    v += __shfl_down_sync(0xffffffffu, v, 8);
    v += __shfl_down_sync(0xffffffffu, v, 4);
    v += __shfl_down_sync(0xffffffffu, v, 2);
    v += __shfl_down_sync(0xffffffffu, v, 1);
    return v;
}

// tanh-GELU (jax.nn.gelu default approximate=True)
__device__ __forceinline__ float gelu_tanh(float x){
    float c = 0.7978845608028654f * (x + 0.044715f * x * x * x);
    return 0.5f * x * (1.0f + tanhf(c));
}

// ======================= prep: transpose/fold weights =======================
__global__ void k_prep(const float* __restrict__ norm_w, const float* __restrict__ V,
                       const float* __restrict__ U, const float* __restrict__ a_logit,
                       const float* __restrict__ W1){
    int d = blockIdx.x * blockDim.x + threadIdx.x;
    if (d < DD){
        float w = norm_w[d];
        #pragma unroll
        for (int r = 0; r < RR; r++){
            g_Vt[r*DD + d] = w * V[d*RR + r];
            g_Ut[r*DD + d] = U[d*RR + r];
        }
        #pragma unroll
        for (int r = 0; r < RFF; r++){
            g_W1t[r*DD + d] = w * W1[d*RFF + r];
        }
    }
    if (d < RR) g_a[d] = 1.0f / (1.0f + expf(-a_logit[d]));
}

// ======================= kernel A: u = V^T rmsnorm(x) =======================
// grid = NROWS/TR, 512 threads; each thread owns one float4 (4 d's) per row.
__global__ void __launch_bounds__(512) k_u(const float* __restrict__ x){
    const int row0 = blockIdx.x * TR;
    const int tid  = threadIdx.x;
    const int w = tid >> 5, l = tid & 31;

    float4 v[RR];
    #pragma unroll
    for (int r = 0; r < RR; r++)
        v[r] = reinterpret_cast<const float4*>(g_Vt + r*DD)[tid];

    float vals[TR*5];
    #pragma unroll
    for (int row = 0; row < TR; row++){
        float4 xv = reinterpret_cast<const float4*>(x)[(size_t)(row0+row)*(DD/4) + tid];
        vals[row*5+0] = xv.x*xv.x + xv.y*xv.y + xv.z*xv.z + xv.w*xv.w;
        #pragma unroll
        for (int r = 0; r < RR; r++)
            vals[row*5+1+r] = xv.x*v[r].x + xv.y*v[r].y + xv.z*v[r].z + xv.w*v[r].w;
    }

    __shared__ float red[16][TR*5];
    #pragma unroll
    for (int i = 0; i < TR*5; i++) vals[i] = warp_sum(vals[i]);
    if (l == 0){
        #pragma unroll
        for (int i = 0; i < TR*5; i++) red[w][i] = vals[i];
    }
    __syncthreads();
    if (tid < TR*5){
        float s = 0.f;
        #pragma unroll
        for (int ww = 0; ww < 16; ww++) s += red[ww][tid];
        red[0][tid] = s;
    }
    __syncthreads();
    if (tid < TR*RR){
        int row = tid >> 2, r = tid & 3;
        float ssq   = red[0][row*5];
        float scale = rsqrtf(ssq * (1.0f/DD) + EPS);
        g_u[(row0+row)*RR + r] = scale * red[0][row*5+1+r];
    }
}

// ======================= kernel B: chunked scan over S =======================
// grid = BB*RR blocks, 128 threads, chunk = 32 steps.
__global__ void __launch_bounds__(128) k_scan(){
    const int b = blockIdx.x >> 2;
    const int r = blockIdx.x & 3;
    const float a = g_a[r];
    const int tid = threadIdx.x;
    const int t0 = tid * 32;
    const float* u = g_u + (size_t)(b*SS)*RR + r;

    // chunk value starting from zero state
    float f = 0.f;
    #pragma unroll 8
    for (int i = 0; i < 32; i++) f = a * f + u[(t0+i)*RR];

    __shared__ float sf[128];
    sf[tid] = f;
    __syncthreads();
    if (tid == 0){
        float A = a;
        #pragma unroll
        for (int k = 0; k < 5; k++) A *= A;   // a^32
        float c = 0.f;
        for (int j = 0; j < 128; j++){
            float fj = sf[j];
            sf[j] = c;              // carry-in for chunk j
            c = A * c + fj;
        }
    }
    __syncthreads();

    float h = sf[tid];
    float* hh = g_h + (size_t)(b*SS)*RR + r;
    #pragma unroll 8
    for (int i = 0; i < 32; i++){
        h = a * h + u[(t0+i)*RR];
        hh[(t0+i)*RR] = h;
    }
}

// ======================= kernel C: x1 = x + U h; out = x1 + FFN(rmsnorm(x1)) =======================
// grid = NROWS/TR, 512 threads, TR=4 rows per block; weights register-tiled across rows.
__global__ void __launch_bounds__(512, 1) k_main(const float* __restrict__ x,
                                                 const float* __restrict__ W2,
                                                 float* __restrict__ out){
    const int row0 = blockIdx.x * TR;
    const int tid  = threadIdx.x;
    const int w = tid >> 5, l = tid & 31;

    __shared__ float x1s[TR][DD];          // 32 KB
    __shared__ float red[TR][128];         // 2 KB reduction scratch
    __shared__ u64   g2s[TR][RFF];         // packed gelu pairs
    __shared__ float sh[TR][RR];
    __shared__ float sscale[TR];

    if (tid < TR*RR) sh[tid>>2][tid&3] = g_h[(row0 + (tid>>2))*RR + (tid&3)];
    __syncthreads();

    // ---------------- Phase 1: x1 = x + U*h, row sumsq ----------------
    float4 ureg[RR];
    #pragma unroll
    for (int r = 0; r < RR; r++)
        ureg[r] = reinterpret_cast<const float4*>(g_Ut + r*DD)[tid];

    float ssq[TR];
    #pragma unroll
    for (int row = 0; row < TR; row++){
        float4 xv = reinterpret_cast<const float4*>(x)[(size_t)(row0+row)*(DD/4) + tid];
        float h0 = sh[row][0], h1 = sh[row][1], h2 = sh[row][2], h3 = sh[row][3];
        float4 y;
        y.x = xv.x + h0*ureg[0].x + h1*ureg[1].x + h2*ureg[2].x + h3*ureg[3].x;
        y.y = xv.y + h0*ureg[0].y + h1*ureg[1].y + h2*ureg[2].y + h3*ureg[3].y;
        y.z = xv.z + h0*ureg[0].z + h1*ureg[1].z + h2*ureg[2].z + h3*ureg[3].z;
        y.w = xv.w + h0*ureg[0].w + h1*ureg[1].w + h2*ureg[2].w + h3*ureg[3].w;
        ssq[row] = y.x*y.x + y.y*y.y + y.z*y.z + y.w*y.w;
        reinterpret_cast<float4*>(&x1s[row][0])[tid] = y;
    }

    #pragma unroll
    for (int row = 0; row < TR; row++) ssq[row] = warp_sum(ssq[row]);
    if (l == 0){
        #pragma unroll
        for (int row = 0; row < TR; row++) red[row][w] = ssq[row];
    }
    __syncthreads();
    if (tid < TR){
        float s = 0.f;
        #pragma unroll
        for (int ww = 0; ww < 16; ww++) s += red[tid][ww];
        sscale[tid] = rsqrtf(s * (1.0f/DD) + EPS);
    }
    __syncthreads();

    // ---------------- Phase 2: t[row][r] = sum_d x1*w*W1[d][r] (f32x2) ----------------
    // threads split into halves over r: half 0 -> r 0..7, half 1 -> r 8..15.
    {
        const int half  = tid >> 8;       // 0 or 1
        const int dt    = tid & 255;      // d-pair lane group
        const int rbase = half * 8;

        u64 w1p[4][8];                    // W1t pairs, held across rows
        #pragma unroll
        for (int p = 0; p < 4; p++){
            int pidx = dt + p*256;        // pair index in [0,1024)
            #pragma unroll
            for (int rr = 0; rr < 8; rr++)
                w1p[p][rr] = reinterpret_cast<const u64*>(g_W1t + (rbase+rr)*DD)[pidx];
        }

        #pragma unroll
        for (int row = 0; row < TR; row++){
            u64 acc[8];
            #pragma unroll
            for (int rr = 0; rr < 8; rr++) acc[rr] = 0ull;   // (0.f,0.f)
            #pragma unroll
            for (int p = 0; p < 4; p++){
                u64 xp = reinterpret_cast<const u64*>(&x1s[row][0])[dt + p*256];
                #pragma unroll
                for (int rr = 0; rr < 8; rr++)
                    acc[rr] = fma2(xp, w1p[p][rr], acc[rr]);
            }
            float tv[8];
            #pragma unroll
            for (int rr = 0; rr < 8; rr++){
                float2 f = unpack2(acc[rr]);
                tv[rr] = warp_sum(f.x + f.y);
            }
            if (l == 0){
                #pragma unroll
                for (int rr = 0; rr < 8; rr++) red[row][w*8 + rr] = tv[rr];
            }
        }
    }
    __syncthreads();

    if (tid < TR*RFF){
        int row = tid >> 4, r = tid & 15;
        int hh = r >> 3, rr = r & 7;
        float s = 0.f;
        #pragma unroll
        for (int ww = 0; ww < 8; ww++) s += red[row][(hh*8 + ww)*8 + rr];
        float g = gelu_tanh(s * sscale[row]);
        g2s[row][r] = pack2(g, g);
    }
    __syncthreads();

    // ---------------- Phase 3: out = x1 + g @ W2 (f32x2, W2 in regs) ----------------
    {
        u64 w2p[2][RFF];                  // this thread's 4 d's (2 pairs) x 16 r
        #pragma unroll
        for (int r = 0; r < RFF; r++){
            float4 wv = reinterpret_cast<const float4*>(W2 + r*DD)[tid];
            w2p[0][r] = pack2(wv.x, wv.y);
            w2p[1][r] = pack2(wv.z, wv.w);
        }
        #pragma unroll
        for (int row = 0; row < TR; row++){
            const u64* xs = reinterpret_cast<const u64*>(&x1s[row][0]);
            u64 a0 = xs[2*tid], a1 = xs[2*tid + 1];
            #pragma unroll
            for (int r = 0; r < RFF; r++){
                u64 g2 = g2s[row][r];
                a0 = fma2(g2, w2p[0][r], a0);
                a1 = fma2(g2, w2p[1][r], a1);
            }
            float2 f0 = unpack2(a0), f1 = unpack2(a1);
            float4 o; o.x = f0.x; o.y = f0.y; o.z = f1.x; o.w = f1.y;
            reinterpret_cast<float4*>(out)[(size_t)(row0+row)*(DD/4) + tid] = o;
        }
    }
}

// ======================= launch =======================
extern "C" void kernel_launch(void* const* d_in, const int* in_sizes, int n_in,
                              void* d_out, int out_size){
    const float* x       = (const float*)d_in[0];
    const float* norm_w  = (const float*)d_in[1];
    const float* V       = (const float*)d_in[2];
    const float* U       = (const float*)d_in[3];
    const float* a_logit = (const float*)d_in[4];
    const float* W1      = (const float*)d_in[5];
    const float* W2      = (const float*)d_in[6];
    float* out = (float*)d_out;

    k_prep<<<8, 256>>>(norm_w, V, U, a_logit, W1);
    k_u<<<NROWS/TR, 512>>>(x);
    k_scan<<<BB*RR, 128>>>();
    k_main<<<NROWS/TR, 512>>>(x, W2, out);
}

// round 3
// speedup vs baseline: 1.2128x; 1.2128x over previous
#include <cuda_runtime.h>
#include <cstdint>

#define BB 4
#define SS 4096
#define DD 2048
#define RR 4
#define RFF 16
#define NROWS (BB*SS)   // 16384
#define TRU 4           // rows per block in k_u
#define TRM 8           // rows per block in k_main
#define EPS 1e-6f

typedef unsigned long long u64;

// -------- device scratch (no allocation allowed) --------
__device__ __align__(16) float g_ssq[NROWS];
__device__ __align__(16) float g_pv [NROWS*RR];
__device__ __align__(16) float g_pu [NROWS*RR];
__device__ __align__(16) float g_pw1[NROWS*RFF];
__device__ __align__(16) float g_h  [NROWS*RR];
__device__ __align__(16) float g_g  [NROWS*RFF];
__device__ __align__(16) float g_Vt [RR*DD];    // w*V transposed
__device__ __align__(16) float g_Ut [RR*DD];    // U transposed
__device__ __align__(16) float g_W1t[RFF*DD];   // w*W1 transposed
__device__ float g_G[16];    // U^T U
__device__ float g_M[64];    // U^T (w*W1)
__device__ float g_a[RR];

// -------- packed f32x2 helpers --------
__device__ __forceinline__ u64 fma2(u64 a, u64 b, u64 c){
    u64 d; asm("fma.rn.f32x2 %0, %1, %2, %3;" : "=l"(d) : "l"(a), "l"(b), "l"(c)); return d;
}
__device__ __forceinline__ u64 pack2(float x, float y){
    u64 r; asm("mov.b64 %0, {%1, %2};" : "=l"(r) : "f"(x), "f"(y)); return r;
}
__device__ __forceinline__ float2 unpack2(u64 p){
    float2 f; asm("mov.b64 {%0, %1}, %2;" : "=f"(f.x), "=f"(f.y) : "l"(p)); return f;
}

__device__ __forceinline__ float warp_sum(float v){
    v += __shfl_down_sync(0xffffffffu, v, 16);
    v += __shfl_down_sync(0xffffffffu, v, 8);
    v += __shfl_down_sync(0xffffffffu, v, 4);
    v += __shfl_down_sync(0xffffffffu, v, 2);
    v += __shfl_down_sync(0xffffffffu, v, 1);
    return v;
}

// butterfly reduce-scatter: v[0..N) per lane; returns, in each lane, the
// warp-total of value index (lane & (N-1)). N power of 2.
template<int N>
__device__ __forceinline__ float rs_reduce(float (&v)[N], int lane){
    #pragma unroll
    for (int s = N/2; s >= 1; s >>= 1){
        bool up = (lane & s) != 0;
        #pragma unroll
        for (int i = 0; i < s; i++){
            float send = up ? v[i] : v[i+s];
            float keep = up ? v[i+s] : v[i];
            v[i] = keep + __shfl_xor_sync(0xffffffffu, send, s);
        }
    }
    float r = v[0];
    #pragma unroll
    for (int s = N; s < 32; s <<= 1)
        r += __shfl_xor_sync(0xffffffffu, r, s);
    return r;
}

__device__ __forceinline__ float gelu_tanh(float x){
    float c = 0.7978845608028654f * (x + 0.044715f * x * x * x);
    return 0.5f * x * (1.0f + tanhf(c));
}

// ======================= prep: transpose/fold weights =======================
__global__ void k_prep(const float* __restrict__ norm_w, const float* __restrict__ V,
                       const float* __restrict__ U, const float* __restrict__ a_logit,
                       const float* __restrict__ W1){
    int d = blockIdx.x * blockDim.x + threadIdx.x;
    if (d < DD){
        float w = norm_w[d];
        #pragma unroll
        for (int r = 0; r < RR; r++){
            g_Vt[r*DD + d] = w * V[d*RR + r];
            g_Ut[r*DD + d] = U[d*RR + r];
        }
        #pragma unroll
        for (int r = 0; r < RFF; r++)
            g_W1t[r*DD + d] = w * W1[d*RFF + r];
    }
    if (d < RR) g_a[d] = 1.0f / (1.0f + expf(-a_logit[d]));
}

// G = U^T U (16 dots), M = U^T (w*W1) (64 dots); one block per dot.
__global__ void k_prep2(const float* __restrict__ U){
    int j = blockIdx.x;
    int tid = threadIdx.x;
    float s = 0.f;
    if (j < 16){
        int k = j >> 2, q = j & 3;
        for (int d = tid; d < DD; d += 256)
            s += U[d*RR + k] * U[d*RR + q];
    } else {
        int k = (j-16) >> 4, r = (j-16) & 15;
        for (int d = tid; d < DD; d += 256)
            s += U[d*RR + k] * g_W1t[r*DD + d];
    }
    s = warp_sum(s);
    __shared__ float sh[8];
    if ((tid & 31) == 0) sh[tid >> 5] = s;
    __syncthreads();
    if (tid == 0){
        float t = 0.f;
        #pragma unroll
        for (int i = 0; i < 8; i++) t += sh[i];
        if (j < 16) g_G[j] = t; else g_M[j-16] = t;
    }
}

// ======================= k_u: 25 dots per row over x =======================
// per row: ssq(x), pV = (wV)^T x (4), pU = U^T x (4), pW1 = (wW1)^T x (16)
__global__ void __launch_bounds__(512) k_u(const float* __restrict__ x){
    const int row0 = blockIdx.x * TRU;
    const int tid = threadIdx.x;
    const int w = tid >> 5, l = tid & 31;
    __shared__ float sred[TRU][25][17];

    u64 xp[TRU][2];
    #pragma unroll
    for (int row = 0; row < TRU; row++){
        float4 xv = reinterpret_cast<const float4*>(x)[(size_t)(row0+row)*(DD/4) + tid];
        xp[row][0] = pack2(xv.x, xv.y);
        xp[row][1] = pack2(xv.z, xv.w);
    }

    // ---- pass A: ssq + pV(4) + pU(4) ----
    {
        u64 wp[8][2];
        #pragma unroll
        for (int r = 0; r < 4; r++){
            wp[r][0]   = reinterpret_cast<const u64*>(g_Vt + r*DD)[2*tid];
            wp[r][1]   = reinterpret_cast<const u64*>(g_Vt + r*DD)[2*tid+1];
            wp[4+r][0] = reinterpret_cast<const u64*>(g_Ut + r*DD)[2*tid];
            wp[4+r][1] = reinterpret_cast<const u64*>(g_Ut + r*DD)[2*tid+1];
        }
        #pragma unroll
        for (int row = 0; row < TRU; row++){
            u64 acc[9];
            acc[0] = fma2(xp[row][0], xp[row][0], fma2(xp[row][1], xp[row][1], 0ull));
            #pragma unroll
            for (int j = 0; j < 8; j++)
                acc[1+j] = fma2(xp[row][0], wp[j][0], fma2(xp[row][1], wp[j][1], 0ull));
            float v[16];
            #pragma unroll
            for (int j = 0; j < 9; j++){ float2 f = unpack2(acc[j]); v[j] = f.x + f.y; }
            #pragma unroll
            for (int j = 9; j < 16; j++) v[j] = 0.f;
            float rv = rs_reduce<16>(v, l);
            if (l < 9) sred[row][l][w] = rv;
        }
    }
    // ---- pass B: pW1, 8 ranks at a time ----
    #pragma unroll
    for (int half = 0; half < 2; half++){
        u64 wp[8][2];
        #pragma unroll
        for (int r = 0; r < 8; r++){
            wp[r][0] = reinterpret_cast<const u64*>(g_W1t + (half*8+r)*DD)[2*tid];
            wp[r][1] = reinterpret_cast<const u64*>(g_W1t + (half*8+r)*DD)[2*tid+1];
        }
        #pragma unroll
        for (int row = 0; row < TRU; row++){
            u64 acc[8];
            #pragma unroll
            for (int j = 0; j < 8; j++)
                acc[j] = fma2(xp[row][0], wp[j][0], fma2(xp[row][1], wp[j][1], 0ull));
            float v[8];
            #pragma unroll
            for (int j = 0; j < 8; j++){ float2 f = unpack2(acc[j]); v[j] = f.x + f.y; }
            float rv = rs_reduce<8>(v, l);
            if (l < 8) sred[row][9 + half*8 + l][w] = rv;
        }
    }
    __syncthreads();

    if (tid < TRU*25){
        int row = tid / 25, val = tid % 25;
        float s = 0.f;
        #pragma unroll
        for (int ww = 0; ww < 16; ww++) s += sred[row][val][ww];
        int gr = row0 + row;
        if (val == 0)      g_ssq[gr] = s;
        else if (val < 5)  g_pv[gr*RR + (val-1)] = s;
        else if (val < 9)  g_pu[gr*RR + (val-5)] = s;
        else               g_pw1[gr*RFF + (val-9)] = s;
    }
}

// ======================= k_scan: chunked recurrence =======================
__global__ void __launch_bounds__(128) k_scan(){
    const int b = blockIdx.x >> 2;
    const int r = blockIdx.x & 3;
    const float a = g_a[r];
    const int tid = threadIdx.x;
    const int t0 = tid * 32;
    const float* pv = g_pv + (size_t)(b*SS)*RR + r;
    const float* sq = g_ssq + (size_t)b*SS;

    float uu[32];
    float f = 0.f;
    #pragma unroll
    for (int i = 0; i < 32; i++){
        int t = t0 + i;
        float sc = rsqrtf(sq[t] * (1.0f/DD) + EPS);
        uu[i] = sc * pv[(size_t)t*RR];
        f = a * f + uu[i];
    }

    __shared__ float sf[128];
    sf[tid] = f;
    __syncthreads();
    if (tid == 0){
        float A = a;
        #pragma unroll
        for (int k = 0; k < 5; k++) A *= A;   // a^32
        float c = 0.f;
        for (int j = 0; j < 128; j++){
            float fj = sf[j];
            sf[j] = c;
            c = A * c + fj;
        }
    }
    __syncthreads();

    float h = sf[tid];
    float* hh = g_h + (size_t)(b*SS)*RR + r;
    #pragma unroll
    for (int i = 0; i < 32; i++){
        h = a * h + uu[i];
        hh[(size_t)(t0+i)*RR] = h;
    }
}

// ======================= k_post: per-row scale1, t, gelu =======================
__global__ void __launch_bounds__(256) k_post(){
    __shared__ float sG[16], sM[64];
    int tid = threadIdx.x;
    if (tid < 16) sG[tid] = g_G[tid];
    if (tid < 64) sM[tid] = g_M[tid];
    __syncthreads();

    int row = blockIdx.x * 256 + tid;
    float4 h4 = reinterpret_cast<const float4*>(g_h)[row];
    float4 p4 = reinterpret_cast<const float4*>(g_pu)[row];
    float h[4] = {h4.x, h4.y, h4.z, h4.w};
    float p[4] = {p4.x, p4.y, p4.z, p4.w};
    float s1 = g_ssq[row];
    #pragma unroll
    for (int k = 0; k < 4; k++) s1 += 2.0f * h[k] * p[k];
    #pragma unroll
    for (int k = 0; k < 4; k++)
        #pragma unroll
        for (int q = 0; q < 4; q++) s1 += h[k] * h[q] * sG[k*4+q];
    float scale = rsqrtf(s1 * (1.0f/DD) + EPS);

    #pragma unroll
    for (int r = 0; r < RFF; r++){
        float t = g_pw1[(size_t)row*RFF + r];
        #pragma unroll
        for (int k = 0; k < 4; k++) t += h[k] * sM[k*16 + r];
        g_g[(size_t)row*RFF + r] = gelu_tanh(t * scale);
    }
}

// ======================= k_main: out = x + U h + g @ W2 (pure stream) =======================
__global__ void __launch_bounds__(512, 1) k_main(const float* __restrict__ x,
                                                 const float* __restrict__ W2,
                                                 float* __restrict__ out){
    const int row0 = blockIdx.x * TRM;
    const int tid = threadIdx.x;
    __shared__ u64 hs2[TRM][4];
    __shared__ u64 g2[TRM][16];

    if (tid < TRM*4){
        int row = tid >> 2, k = tid & 3;
        float hv = g_h[(size_t)(row0+row)*RR + k];
        hs2[row][k] = pack2(hv, hv);
    }
    if (tid < TRM*16){
        int row = tid >> 4, r = tid & 15;
        float gv = g_g[(size_t)(row0+row)*RFF + r];
        g2[row][r] = pack2(gv, gv);
    }

    u64 utp[4][2], w2p[16][2];
    #pragma unroll
    for (int k = 0; k < 4; k++){
        utp[k][0] = reinterpret_cast<const u64*>(g_Ut + k*DD)[2*tid];
        utp[k][1] = reinterpret_cast<const u64*>(g_Ut + k*DD)[2*tid+1];
    }
    #pragma unroll
    for (int r = 0; r < RFF; r++){
        w2p[r][0] = reinterpret_cast<const u64*>(W2 + r*DD)[2*tid];
        w2p[r][1] = reinterpret_cast<const u64*>(W2 + r*DD)[2*tid+1];
    }
    __syncthreads();

    const float4* xr = reinterpret_cast<const float4*>(x) + (size_t)row0*(DD/4) + tid;
    float4* orow = reinterpret_cast<float4*>(out) + (size_t)row0*(DD/4) + tid;

    float4 xa = xr[0];
    #pragma unroll
    for (int row = 0; row < TRM; row++){
        float4 xb = xa;
        if (row + 1 < TRM) xb = xr[(row+1)*(DD/4)];
        u64 a0 = pack2(xa.x, xa.y), a1 = pack2(xa.z, xa.w);
        #pragma unroll
        for (int k = 0; k < 4; k++){
            u64 hp = hs2[row][k];
            a0 = fma2(hp, utp[k][0], a0);
            a1 = fma2(hp, utp[k][1], a1);
        }
        #pragma unroll
        for (int r = 0; r < RFF; r++){
            u64 gp = g2[row][r];
            a0 = fma2(gp, w2p[r][0], a0);
            a1 = fma2(gp, w2p[r][1], a1);
        }
        float2 f0 = unpack2(a0), f1 = unpack2(a1);
        float4 o; o.x = f0.x; o.y = f0.y; o.z = f1.x; o.w = f1.y;
        orow[row*(DD/4)] = o;
        xa = xb;
    }
}

// ======================= launch =======================
extern "C" void kernel_launch(void* const* d_in, const int* in_sizes, int n_in,
                              void* d_out, int out_size){
    const float* x       = (const float*)d_in[0];
    const float* norm_w  = (const float*)d_in[1];
    const float* V       = (const float*)d_in[2];
    const float* U       = (const float*)d_in[3];
    const float* a_logit = (const float*)d_in[4];
    const float* W1      = (const float*)d_in[5];
    const float* W2      = (const float*)d_in[6];
    float* out = (float*)d_out;

    k_prep <<<8, 256>>>(norm_w, V, U, a_logit, W1);
    k_prep2<<<80, 256>>>(U);
    k_u    <<<NROWS/TRU, 512>>>(x);
    k_scan <<<BB*RR, 128>>>();
    k_post <<<NROWS/256, 256>>>();
    k_main <<<NROWS/TRM, 512>>>(x, W2, out);
}